// round 8
// baseline (speedup 1.0000x reference)
#include <cuda_runtime.h>
#include <cuda_fp16.h>
#include <math.h>

// ---------------- problem constants ----------------
#define kB     64
#define kBN    8192        // B*N nodes
#define kE     262144      // edges
#define kH     128
#define kNRBF  64
#define kNBLK  4
#define kNGRID 1024        // filter table resolution
#define kCAP   128         // max edges per node bucket (lambda=32)
#define kRCUT  6.0f
#define kGAMMA (10.0f / 36.0f)

#define kMT    32          // GEMM M-tile rows (grid = kBN/kMT = 256 > 148 SMs)

// ---------------- device scratch ----------------
__device__ float  g_h  [kBN * kH];
__device__ __half g_hsh[kBN * kH];               // h @ lin_in, fp16
__device__ float  g_agg[kBN * kH];
__device__ __half g_tabh[kNBLK * kNGRID * kH];   // w(d) table, fp16
__device__ int    g_deg[kBN];

struct __align__(8) SEdge { int s; float t; };
__device__ SEdge g_se[kBN * kCAP];   // bucketed edges per dst node

__device__ __forceinline__ float silu(float x) { return x / (1.0f + expf(-x)); }

// ---------------- prep kernels ----------------
__global__ void zero_out_kernel(float* out) {
    if (threadIdx.x < kB) out[threadIdx.x] = 0.0f;
}

__global__ void embed_kernel(const int* __restrict__ Z, const float* __restrict__ ew) {
    int n = blockIdx.x;
    int c = threadIdx.x;
    g_h[n * kH + c] = ew[Z[n] * kH + c];
    if (c == 0) g_deg[n] = 0;
}

// direct bucket scatter: 2 edges per thread, batched loads for ILP
__global__ void scatter_kernel(const int* __restrict__ ei, const float* __restrict__ pos) {
    int t2 = blockIdx.x * blockDim.x + threadIdx.x;
    int2 sp = *(const int2*)(ei + t2 * 2);        // src pair
    int2 dp = *(const int2*)(ei + kE + t2 * 2);   // dst pair
    float s0x = pos[sp.x * 3 + 0], s0y = pos[sp.x * 3 + 1], s0z = pos[sp.x * 3 + 2];
    float d0x = pos[dp.x * 3 + 0], d0y = pos[dp.x * 3 + 1], d0z = pos[dp.x * 3 + 2];
    float s1x = pos[sp.y * 3 + 0], s1y = pos[sp.y * 3 + 1], s1z = pos[sp.y * 3 + 2];
    float d1x = pos[dp.y * 3 + 0], d1y = pos[dp.y * 3 + 1], d1z = pos[dp.y * 3 + 2];
    float ax = s0x - d0x, ay = s0y - d0y, az = s0z - d0z;
    float bx = s1x - d1x, by = s1y - d1y, bz = s1z - d1z;
    float r0 = fminf(sqrtf(ax * ax + ay * ay + az * az), kRCUT);
    float r1 = fminf(sqrtf(bx * bx + by * by + bz * bz), kRCUT);
    const float sc = (float)(kNGRID - 1) / kRCUT;
    int p0 = atomicAdd(&g_deg[dp.x], 1);
    int p1 = atomicAdd(&g_deg[dp.y], 1);
    SEdge e0; e0.s = sp.x; e0.t = r0 * sc;
    SEdge e1; e1.s = sp.y; e1.t = r1 * sc;
    if (p0 < kCAP) g_se[dp.x * kCAP + p0] = e0;
    if (p1 < kCAP) g_se[dp.y * kCAP + p1] = e1;
}

// ---------------- edge-filter lookup table (fp16) ----------------
__global__ void __launch_bounds__(256) table_kernel(
        const float* __restrict__ w1, const float* __restrict__ b1,
        const float* __restrict__ w2, const float* __restrict__ b2) {
    extern __shared__ float sm[];
    float* sW1  = sm;                       // 64*128
    float* sW2  = sW1 + kNRBF * kH;         // 128*128
    float* sh   = sW2 + kH * kH;            // 2*128
    float* srbf = sh + 2 * kH;              // 2*64
    int blk  = blockIdx.y;
    int tid  = threadIdx.x;
    int c    = tid & 127;
    int half = tid >> 7;
    const float* W1 = w1 + blk * kNRBF * kH;
    const float* W2 = w2 + blk * kH * kH;
    float bb1 = b1[blk * kH + c];
    float bb2 = b2[blk * kH + c];
    for (int i = tid; i < kNRBF * kH; i += 256) sW1[i] = W1[i];
    for (int i = tid; i < kH * kH;   i += 256) sW2[i] = W2[i];
    __syncthreads();

    int g0 = blockIdx.x * 32;
    for (int it = 0; it < 16; it++) {
        int g = g0 + it * 2 + half;
        float dd = kRCUT * (float)g / (float)(kNGRID - 1);
        if (c < kNRBF) {
            float ck = kRCUT * (float)c / (float)(kNRBF - 1);
            float u  = dd - ck;
            srbf[half * kNRBF + c] = expf(-kGAMMA * u * u);
        }
        __syncthreads();
        float a0 = 0, a1 = 0, a2 = 0, a3 = 0;
        const float* rb = srbf + half * kNRBF;
#pragma unroll
        for (int k = 0; k < kNRBF; k += 4) {
            a0 += rb[k + 0] * sW1[(k + 0) * kH + c];
            a1 += rb[k + 1] * sW1[(k + 1) * kH + c];
            a2 += rb[k + 2] * sW1[(k + 2) * kH + c];
            a3 += rb[k + 3] * sW1[(k + 3) * kH + c];
        }
        sh[half * kH + c] = silu(a0 + a1 + a2 + a3 + bb1);
        __syncthreads();
        float o0 = 0, o1 = 0, o2 = 0, o3 = 0;
        const float* hh = sh + half * kH;
#pragma unroll
        for (int j = 0; j < kH; j += 4) {
            o0 += hh[j + 0] * sW2[(j + 0) * kH + c];
            o1 += hh[j + 1] * sW2[(j + 1) * kH + c];
            o2 += hh[j + 2] * sW2[(j + 2) * kH + c];
            o3 += hh[j + 3] * sW2[(j + 3) * kH + c];
        }
        g_tabh[(blk * kNGRID + g) * kH + c] = __float2half_rn(o0 + o1 + o2 + o3 + bb2);
        __syncthreads();
    }
}

// ---------------- initial GEMM hs = h @ lin_in[0], fp16 out ----------------
// 32-row tile, 256 thr, thread tile 2x8; smem 80KB -> 2 CTAs/SM; grid 256
__global__ void __launch_bounds__(256) gemm_h_kernel(const float* __restrict__ A,
                                                     const float* __restrict__ W,
                                                     __half* __restrict__ C) {
    extern __shared__ float sm[];
    float* As = sm;             // 32*128 fp32
    float* Bs = sm + kMT * kH;  // 128*128 fp32
    int tid = threadIdx.x;
    int m0  = blockIdx.x * kMT;

    const float4* A4  = (const float4*)(A + m0 * kH);
    float4*       As4 = (float4*)As;
#pragma unroll
    for (int i = 0; i < 4; i++) As4[tid + i * 256] = A4[tid + i * 256];
    const float4* W4  = (const float4*)W;
    float4*       Bs4 = (float4*)Bs;
#pragma unroll
    for (int i = 0; i < 16; i++) Bs4[tid + i * 256] = W4[tid + i * 256];
    __syncthreads();

    int ty = tid >> 4;   // 0..15 -> 2 rows each
    int tx = tid & 15;   // 0..15 -> 8 cols each
    float acc[2][8];
#pragma unroll
    for (int i = 0; i < 2; i++)
#pragma unroll
        for (int j = 0; j < 8; j++) acc[i][j] = 0.0f;

#pragma unroll 8
    for (int k = 0; k < kH; k++) {
        float a0 = As[(ty * 2 + 0) * kH + k];
        float a1 = As[(ty * 2 + 1) * kH + k];
        float4 b0 = *(const float4*)&Bs[k * kH + tx * 8];
        float4 b1 = *(const float4*)&Bs[k * kH + tx * 8 + 4];
        float bv[8] = {b0.x, b0.y, b0.z, b0.w, b1.x, b1.y, b1.z, b1.w};
#pragma unroll
        for (int j = 0; j < 8; j++) { acc[0][j] += a0 * bv[j]; acc[1][j] += a1 * bv[j]; }
    }

#pragma unroll
    for (int i = 0; i < 2; i++) {
        int r = m0 + ty * 2 + i;
        __half2 p0 = __floats2half2_rn(acc[i][0], acc[i][1]);
        __half2 p1 = __floats2half2_rn(acc[i][2], acc[i][3]);
        __half2 p2 = __floats2half2_rn(acc[i][4], acc[i][5]);
        __half2 p3 = __floats2half2_rn(acc[i][6], acc[i][7]);
        uint4 u;
        u.x = *reinterpret_cast<unsigned*>(&p0);
        u.y = *reinterpret_cast<unsigned*>(&p1);
        u.z = *reinterpret_cast<unsigned*>(&p2);
        u.w = *reinterpret_cast<unsigned*>(&p3);
        *reinterpret_cast<uint4*>(&C[r * kH + tx * 8]) = u;
    }
}

// ---------------- edge aggregation: warp/node, fp16 table + fp16 hs ----------------
__global__ void __launch_bounds__(128) agg_kernel(int blk) {
    int warp = threadIdx.x >> 5;
    int lane = threadIdx.x & 31;
    int n    = blockIdx.x * 4 + warp;
    const uint2* tab = (const uint2*)(g_tabh + blk * kNGRID * kH);
    const uint2* hs  = (const uint2*)g_hsh;
    int len  = g_deg[n];
    if (len > kCAP) len = kCAP;
    const SEdge* row = g_se + n * kCAP;
    float4 acc = make_float4(0.f, 0.f, 0.f, 0.f);
    for (int p = 0; p < len; p++) {
        SEdge e = row[p];
        float t = e.t;
        int   gdx = (int)t;
        if (gdx > kNGRID - 2) gdx = kNGRID - 2;
        float f = t - (float)gdx;
        uint2 u0 = tab[gdx * 32 + lane];
        uint2 u1 = tab[(gdx + 1) * 32 + lane];
        uint2 uh = hs[e.s * 32 + lane];
        float2 w0a = __half22float2(*reinterpret_cast<__half2*>(&u0.x));
        float2 w0b = __half22float2(*reinterpret_cast<__half2*>(&u0.y));
        float2 w1a = __half22float2(*reinterpret_cast<__half2*>(&u1.x));
        float2 w1b = __half22float2(*reinterpret_cast<__half2*>(&u1.y));
        float2 hva = __half22float2(*reinterpret_cast<__half2*>(&uh.x));
        float2 hvb = __half22float2(*reinterpret_cast<__half2*>(&uh.y));
        acc.x += (w0a.x + (w1a.x - w0a.x) * f) * hva.x;
        acc.y += (w0a.y + (w1a.y - w0a.y) * f) * hva.y;
        acc.z += (w0b.x + (w1b.x - w0b.x) * f) * hvb.x;
        acc.w += (w0b.y + (w1b.y - w0b.y) * f) * hvb.y;
    }
    ((float4*)g_agg)[n * 32 + lane] = acc;
}

// ---------------- fused node MLP + residual + LayerNorm + next lin_in ----------------
// 32-row tile; stage1: t1 = silu(agg@W1+b1); stage2: h = LN(h + t1@W2+b2);
// stage3 (if !LAST): hs = h @ Wnext -> fp16
template <int LAST>
__global__ void __launch_bounds__(256) node_fused_kernel(
        const float* __restrict__ W1, const float* __restrict__ b1,
        const float* __restrict__ W2, const float* __restrict__ b2,
        const float* __restrict__ lng, const float* __restrict__ lnb,
        const float* __restrict__ Wnext) {
    extern __shared__ float sm[];
    float* As = sm;             // 32*128 fp32 (agg -> t1 -> h)
    float* Bs = sm + kMT * kH;  // 128*128 fp32 (W1 -> W2 -> Wnext)
    int tid = threadIdx.x;
    int m0  = blockIdx.x * kMT;
    int ty  = tid >> 4;
    int tx  = tid & 15;

    const float4* A4  = (const float4*)(g_agg + m0 * kH);
    float4*       As4 = (float4*)As;
#pragma unroll
    for (int i = 0; i < 4; i++) As4[tid + i * 256] = A4[tid + i * 256];
    const float4* W14 = (const float4*)W1;
    float4*       Bs4 = (float4*)Bs;
#pragma unroll
    for (int i = 0; i < 16; i++) Bs4[tid + i * 256] = W14[tid + i * 256];
    __syncthreads();

    float acc[2][8];
#pragma unroll
    for (int i = 0; i < 2; i++)
#pragma unroll
        for (int j = 0; j < 8; j++) acc[i][j] = 0.0f;
#pragma unroll 8
    for (int k = 0; k < kH; k++) {
        float a0 = As[(ty * 2 + 0) * kH + k];
        float a1 = As[(ty * 2 + 1) * kH + k];
        float4 b0v = *(const float4*)&Bs[k * kH + tx * 8];
        float4 b1v = *(const float4*)&Bs[k * kH + tx * 8 + 4];
        float bv[8] = {b0v.x, b0v.y, b0v.z, b0v.w, b1v.x, b1v.y, b1v.z, b1v.w};
#pragma unroll
        for (int j = 0; j < 8; j++) { acc[0][j] += a0 * bv[j]; acc[1][j] += a1 * bv[j]; }
    }
    __syncthreads();   // all stage-1 reads of As/Bs done

    // t1 = silu(acc + b1) -> As ; W2 -> Bs
    {
        float4 bb0 = *(const float4*)&b1[tx * 8];
        float4 bb1 = *(const float4*)&b1[tx * 8 + 4];
        float bb[8] = {bb0.x, bb0.y, bb0.z, bb0.w, bb1.x, bb1.y, bb1.z, bb1.w};
#pragma unroll
        for (int i = 0; i < 2; i++) {
            int r = ty * 2 + i;
#pragma unroll
            for (int j = 0; j < 8; j++)
                As[r * kH + tx * 8 + j] = silu(acc[i][j] + bb[j]);
        }
        const float4* W24 = (const float4*)W2;
#pragma unroll
        for (int i = 0; i < 16; i++) Bs4[tid + i * 256] = W24[tid + i * 256];
    }
    __syncthreads();

#pragma unroll
    for (int i = 0; i < 2; i++)
#pragma unroll
        for (int j = 0; j < 8; j++) acc[i][j] = 0.0f;
#pragma unroll 8
    for (int k = 0; k < kH; k++) {
        float a0 = As[(ty * 2 + 0) * kH + k];
        float a1 = As[(ty * 2 + 1) * kH + k];
        float4 b0v = *(const float4*)&Bs[k * kH + tx * 8];
        float4 b1v = *(const float4*)&Bs[k * kH + tx * 8 + 4];
        float bv[8] = {b0v.x, b0v.y, b0v.z, b0v.w, b1v.x, b1v.y, b1v.z, b1v.w};
#pragma unroll
        for (int j = 0; j < 8; j++) { acc[0][j] += a0 * bv[j]; acc[1][j] += a1 * bv[j]; }
    }
    __syncthreads();   // stage-2 reads done; safe to overwrite As/Bs

    // epilogue: + b2 + residual, LayerNorm across 16 tx-threads per row
    float4 bb0 = *(const float4*)&b2[tx * 8];
    float4 bb1 = *(const float4*)&b2[tx * 8 + 4];
    float bb[8] = {bb0.x, bb0.y, bb0.z, bb0.w, bb1.x, bb1.y, bb1.z, bb1.w};
    float4 gg0 = *(const float4*)&lng[tx * 8];
    float4 gg1 = *(const float4*)&lng[tx * 8 + 4];
    float gg[8] = {gg0.x, gg0.y, gg0.z, gg0.w, gg1.x, gg1.y, gg1.z, gg1.w};
    float4 lb0 = *(const float4*)&lnb[tx * 8];
    float4 lb1 = *(const float4*)&lnb[tx * 8 + 4];
    float lb[8] = {lb0.x, lb0.y, lb0.z, lb0.w, lb1.x, lb1.y, lb1.z, lb1.w};

#pragma unroll
    for (int i = 0; i < 2; i++) {
        int r = m0 + ty * 2 + i;
        float4 h0 = *(const float4*)&g_h[r * kH + tx * 8];
        float4 h1 = *(const float4*)&g_h[r * kH + tx * 8 + 4];
        float hv[8] = {h0.x, h0.y, h0.z, h0.w, h1.x, h1.y, h1.z, h1.w};
        float v[8];
        float s = 0.0f;
#pragma unroll
        for (int j = 0; j < 8; j++) { v[j] = acc[i][j] + bb[j] + hv[j]; s += v[j]; }
#pragma unroll
        for (int o = 1; o < 16; o <<= 1) s += __shfl_xor_sync(0xffffffffu, s, o);
        float mu = s * (1.0f / 128.0f);
        float q = 0.0f;
        float d[8];
#pragma unroll
        for (int j = 0; j < 8; j++) { d[j] = v[j] - mu; q += d[j] * d[j]; }
#pragma unroll
        for (int o = 1; o < 16; o <<= 1) q += __shfl_xor_sync(0xffffffffu, q, o);
        float rstd = rsqrtf(q * (1.0f / 128.0f) + 1e-5f);
        float w[8];
#pragma unroll
        for (int j = 0; j < 8; j++) w[j] = d[j] * rstd * gg[j] + lb[j];
        *(float4*)&g_h[r * kH + tx * 8]     = make_float4(w[0], w[1], w[2], w[3]);
        *(float4*)&g_h[r * kH + tx * 8 + 4] = make_float4(w[4], w[5], w[6], w[7]);
        if (!LAST) {
            int rl = ty * 2 + i;
#pragma unroll
            for (int j = 0; j < 8; j++) As[rl * kH + tx * 8 + j] = w[j];
        }
    }

    if (!LAST) {
        const float4* WN4 = (const float4*)Wnext;
#pragma unroll
        for (int i = 0; i < 16; i++) Bs4[tid + i * 256] = WN4[tid + i * 256];
        __syncthreads();

#pragma unroll
        for (int i = 0; i < 2; i++)
#pragma unroll
            for (int j = 0; j < 8; j++) acc[i][j] = 0.0f;
#pragma unroll 8
        for (int k = 0; k < kH; k++) {
            float a0 = As[(ty * 2 + 0) * kH + k];
            float a1 = As[(ty * 2 + 1) * kH + k];
            float4 b0v = *(const float4*)&Bs[k * kH + tx * 8];
            float4 b1v = *(const float4*)&Bs[k * kH + tx * 8 + 4];
            float bv[8] = {b0v.x, b0v.y, b0v.z, b0v.w, b1v.x, b1v.y, b1v.z, b1v.w};
#pragma unroll
            for (int j = 0; j < 8; j++) { acc[0][j] += a0 * bv[j]; acc[1][j] += a1 * bv[j]; }
        }
#pragma unroll
        for (int i = 0; i < 2; i++) {
            int r = m0 + ty * 2 + i;
            __half2 p0 = __floats2half2_rn(acc[i][0], acc[i][1]);
            __half2 p1 = __floats2half2_rn(acc[i][2], acc[i][3]);
            __half2 p2 = __floats2half2_rn(acc[i][4], acc[i][5]);
            __half2 p3 = __floats2half2_rn(acc[i][6], acc[i][7]);
            uint4 u;
            u.x = *reinterpret_cast<unsigned*>(&p0);
            u.y = *reinterpret_cast<unsigned*>(&p1);
            u.z = *reinterpret_cast<unsigned*>(&p2);
            u.w = *reinterpret_cast<unsigned*>(&p3);
            *reinterpret_cast<uint4*>(&g_hsh[r * kH + tx * 8]) = u;
        }
    }
}

// ---------------- readout ----------------
__global__ void readout_kernel(float* __restrict__ out,
                               const float* __restrict__ w1, const float* __restrict__ b1,
                               const float* __restrict__ w2, const float* __restrict__ b2) {
    __shared__ float s[kH];
    __shared__ float red[2];
    int n   = blockIdx.x;
    int tid = threadIdx.x;
    s[tid] = silu(g_h[n * kH + tid]);
    __syncthreads();
    float e = 0.0f;
    if (tid < 64) {
        float x = b1[tid];
#pragma unroll 8
        for (int k = 0; k < kH; k++) x += s[k] * w1[k * 64 + tid];
        e = silu(x) * w2[tid];
    }
#pragma unroll
    for (int off = 16; off; off >>= 1) e += __shfl_down_sync(0xffffffffu, e, off);
    if (tid == 0)  red[0] = e;
    if (tid == 32) red[1] = e;
    __syncthreads();
    if (tid == 0) atomicAdd(&out[n >> 7], red[0] + red[1] + b2[0]);
}

// ---------------- launcher ----------------
extern "C" void kernel_launch(void* const* d_in, const int* in_sizes, int n_in,
                              void* d_out, int out_size) {
    (void)in_sizes; (void)n_in; (void)out_size;
    const int*   Z        = (const int*)  d_in[0];
    const float* pos      = (const float*)d_in[1];
    const int*   ei       = (const int*)  d_in[2];
    const float* embed_w  = (const float*)d_in[3];
    const float* edge_w1  = (const float*)d_in[4];
    const float* edge_b1  = (const float*)d_in[5];
    const float* edge_w2  = (const float*)d_in[6];
    const float* edge_b2  = (const float*)d_in[7];
    const float* lin_in_w = (const float*)d_in[8];
    const float* node_w1  = (const float*)d_in[9];
    const float* node_b1  = (const float*)d_in[10];
    const float* node_w2  = (const float*)d_in[11];
    const float* node_b2  = (const float*)d_in[12];
    const float* ln_g     = (const float*)d_in[13];
    const float* ln_b     = (const float*)d_in[14];
    const float* ro_w1    = (const float*)d_in[15];
    const float* ro_b1    = (const float*)d_in[16];
    const float* ro_w2    = (const float*)d_in[17];
    const float* ro_b2    = (const float*)d_in[18];
    float* out = (float*)d_out;

    float *ph;
    __half *phs;
    cudaGetSymbolAddress((void**)&ph,  g_h);
    cudaGetSymbolAddress((void**)&phs, g_hsh);

    const int GEMM_SMEM = (kMT * kH + kH * kH) * (int)sizeof(float);   // 80 KB
    const int TAB_SMEM  = (kNRBF * kH + kH * kH + 2 * kH + 2 * kNRBF) * (int)sizeof(float);
    cudaFuncSetAttribute(gemm_h_kernel,        cudaFuncAttributeMaxDynamicSharedMemorySize, GEMM_SMEM);
    cudaFuncSetAttribute(node_fused_kernel<0>, cudaFuncAttributeMaxDynamicSharedMemorySize, GEMM_SMEM);
    cudaFuncSetAttribute(node_fused_kernel<1>, cudaFuncAttributeMaxDynamicSharedMemorySize, GEMM_SMEM);
    cudaFuncSetAttribute(table_kernel,         cudaFuncAttributeMaxDynamicSharedMemorySize, TAB_SMEM);

    // ---- prep: embedding (+deg zero), bucket scatter, filter tables ----
    embed_kernel<<<kBN, kH>>>(Z, embed_w);
    scatter_kernel<<<kE / 512, 256>>>(ei, pos);
    table_kernel<<<dim3(kNGRID / 32, kNBLK), 256, TAB_SMEM>>>(edge_w1, edge_b1, edge_w2, edge_b2);
    gemm_h_kernel<<<kBN / kMT, 256, GEMM_SMEM>>>(ph, lin_in_w, phs);   // hs for block 0

    // ---- 4 interaction blocks ----
    for (int b = 0; b < kNBLK; b++) {
        agg_kernel<<<kBN / 4, 128>>>(b);
        if (b < kNBLK - 1) {
            node_fused_kernel<0><<<kBN / kMT, 256, GEMM_SMEM>>>(
                node_w1 + b * kH * kH, node_b1 + b * kH,
                node_w2 + b * kH * kH, node_b2 + b * kH,
                ln_g + b * kH, ln_b + b * kH,
                lin_in_w + (b + 1) * kH * kH);
        } else {
            node_fused_kernel<1><<<kBN / kMT, 256, GEMM_SMEM>>>(
                node_w1 + b * kH * kH, node_b1 + b * kH,
                node_w2 + b * kH * kH, node_b2 + b * kH,
                ln_g + b * kH, ln_b + b * kH, nullptr);
        }
    }

    // ---- readout ----
    zero_out_kernel<<<1, 64>>>(out);
    readout_kernel<<<kBN, kH>>>(out, ro_w1, ro_b1, ro_w2, ro_b2);
}

// round 10
// speedup vs baseline: 1.4696x; 1.4696x over previous
#include <cuda_runtime.h>
#include <cuda_fp16.h>
#include <math.h>

// ---------------- problem constants ----------------
#define kB     64
#define kBN    8192        // B*N nodes
#define kE     262144      // edges
#define kH     128
#define kNRBF  64
#define kNBLK  4
#define kNGRID 512         // filter table resolution
#define kCAP   128         // max edges per node bucket (lambda=32)
#define kRCUT  6.0f
#define kGAMMA (10.0f / 36.0f)

// ---------------- device scratch ----------------
__device__ float  g_h  [kBN * kH];
__device__ __half g_hsh[kBN * kH];               // h @ lin_in, fp16
__device__ float  g_agg[kBN * kH];
__device__ __half g_tabh[kNBLK * kNGRID * kH];   // w(d) table, fp16
__device__ int    g_deg[kBN];

struct __align__(8) SEdge { int s; float t; };
__device__ SEdge g_se[kBN * kCAP];   // bucketed edges per dst node

__device__ __forceinline__ float silu(float x) { return x / (1.0f + expf(-x)); }

// load 128x128 fp32 weight matrix from global into fp16 smem (uint2 per float4)
__device__ __forceinline__ void load_w_half(const float* __restrict__ W,
                                            __half* __restrict__ Bsh, int tid) {
    const float4* W4 = (const float4*)W;
    uint2* B2 = (uint2*)Bsh;
#pragma unroll
    for (int i = 0; i < 16; i++) {
        float4 w = W4[tid + i * 256];
        __half2 a = __floats2half2_rn(w.x, w.y);
        __half2 b = __floats2half2_rn(w.z, w.w);
        uint2 u;
        u.x = *reinterpret_cast<unsigned*>(&a);
        u.y = *reinterpret_cast<unsigned*>(&b);
        B2[tid + i * 256] = u;
    }
}

// read 8 fp16 weights at [k][tx*8..] and widen to fp32
__device__ __forceinline__ void read_w8(const __half* __restrict__ Bsh, int k, int tx,
                                        float bv[8]) {
    uint4 bq = *(const uint4*)&Bsh[k * kH + tx * 8];
    float2 f0 = __half22float2(*reinterpret_cast<__half2*>(&bq.x));
    float2 f1 = __half22float2(*reinterpret_cast<__half2*>(&bq.y));
    float2 f2 = __half22float2(*reinterpret_cast<__half2*>(&bq.z));
    float2 f3 = __half22float2(*reinterpret_cast<__half2*>(&bq.w));
    bv[0] = f0.x; bv[1] = f0.y; bv[2] = f1.x; bv[3] = f1.y;
    bv[4] = f2.x; bv[5] = f2.y; bv[6] = f3.x; bv[7] = f3.y;
}

// ---------------- mma helpers (m16n8k16 f16 -> f32) ----------------
__device__ __forceinline__ void mma16816(float* d, const unsigned* a,
                                         unsigned b0, unsigned b1) {
    asm volatile(
        "mma.sync.aligned.m16n8k16.row.col.f32.f16.f16.f32 "
        "{%0,%1,%2,%3}, {%4,%5,%6,%7}, {%8,%9}, {%0,%1,%2,%3};\n"
        : "+f"(d[0]), "+f"(d[1]), "+f"(d[2]), "+f"(d[3])
        : "r"(a[0]), "r"(a[1]), "r"(a[2]), "r"(a[3]), "r"(b0), "r"(b1));
}

// split float2 -> fp16 hi + fp16 residual (packed half2 as u32)
__device__ __forceinline__ void split2(float2 f, unsigned& hi, unsigned& lo) {
    __half hx = __float2half_rn(f.x);
    __half hy = __float2half_rn(f.y);
    __half lx = __float2half_rn(f.x - __half2float(hx));
    __half ly = __float2half_rn(f.y - __half2float(hy));
    __half2 H = __halves2half2(hx, hy);
    __half2 L = __halves2half2(lx, ly);
    hi = *reinterpret_cast<unsigned*>(&H);
    lo = *reinterpret_cast<unsigned*>(&L);
}

// ---------------- prep kernels ----------------
__global__ void zero_out_kernel(float* out) {
    if (threadIdx.x < kB) out[threadIdx.x] = 0.0f;
}

__global__ void embed_kernel(const int* __restrict__ Z, const float* __restrict__ ew) {
    int n = blockIdx.x;
    int c = threadIdx.x;
    g_h[n * kH + c] = ew[Z[n] * kH + c];
    if (c == 0) g_deg[n] = 0;
}

// direct bucket scatter: 2 edges per thread, batched loads for ILP
__global__ void scatter_kernel(const int* __restrict__ ei, const float* __restrict__ pos) {
    int t2 = blockIdx.x * blockDim.x + threadIdx.x;
    int2 sp = *(const int2*)(ei + t2 * 2);        // src pair
    int2 dp = *(const int2*)(ei + kE + t2 * 2);   // dst pair
    float s0x = pos[sp.x * 3 + 0], s0y = pos[sp.x * 3 + 1], s0z = pos[sp.x * 3 + 2];
    float d0x = pos[dp.x * 3 + 0], d0y = pos[dp.x * 3 + 1], d0z = pos[dp.x * 3 + 2];
    float s1x = pos[sp.y * 3 + 0], s1y = pos[sp.y * 3 + 1], s1z = pos[sp.y * 3 + 2];
    float d1x = pos[dp.y * 3 + 0], d1y = pos[dp.y * 3 + 1], d1z = pos[dp.y * 3 + 2];
    float ax = s0x - d0x, ay = s0y - d0y, az = s0z - d0z;
    float bx = s1x - d1x, by = s1y - d1y, bz = s1z - d1z;
    float r0 = fminf(sqrtf(ax * ax + ay * ay + az * az), kRCUT);
    float r1 = fminf(sqrtf(bx * bx + by * by + bz * bz), kRCUT);
    const float sc = (float)(kNGRID - 1) / kRCUT;
    int p0 = atomicAdd(&g_deg[dp.x], 1);
    int p1 = atomicAdd(&g_deg[dp.y], 1);
    SEdge e0; e0.s = sp.x; e0.t = r0 * sc;
    SEdge e1; e1.s = sp.y; e1.t = r1 * sc;
    if (p0 < kCAP) g_se[dp.x * kCAP + p0] = e0;
    if (p1 < kCAP) g_se[dp.y * kCAP + p1] = e1;
}

// ---------------- edge-filter lookup table (fp16) ----------------
__global__ void __launch_bounds__(256) table_kernel(
        const float* __restrict__ w1, const float* __restrict__ b1,
        const float* __restrict__ w2, const float* __restrict__ b2) {
    extern __shared__ float sm[];
    float* sW1  = sm;                       // 64*128
    float* sW2  = sW1 + kNRBF * kH;         // 128*128
    float* sh   = sW2 + kH * kH;            // 2*128
    float* srbf = sh + 2 * kH;              // 2*64
    int blk  = blockIdx.y;
    int tid  = threadIdx.x;
    int c    = tid & 127;
    int half = tid >> 7;
    const float* W1 = w1 + blk * kNRBF * kH;
    const float* W2 = w2 + blk * kH * kH;
    float bb1 = b1[blk * kH + c];
    float bb2 = b2[blk * kH + c];
    for (int i = tid; i < kNRBF * kH; i += 256) sW1[i] = W1[i];
    for (int i = tid; i < kH * kH;   i += 256) sW2[i] = W2[i];
    __syncthreads();

    int g0 = blockIdx.x * 32;
    for (int it = 0; it < 16; it++) {
        int g = g0 + it * 2 + half;
        float dd = kRCUT * (float)g / (float)(kNGRID - 1);
        if (c < kNRBF) {
            float ck = kRCUT * (float)c / (float)(kNRBF - 1);
            float u  = dd - ck;
            srbf[half * kNRBF + c] = expf(-kGAMMA * u * u);
        }
        __syncthreads();
        float a0 = 0, a1 = 0, a2 = 0, a3 = 0;
        const float* rb = srbf + half * kNRBF;
#pragma unroll
        for (int k = 0; k < kNRBF; k += 4) {
            a0 += rb[k + 0] * sW1[(k + 0) * kH + c];
            a1 += rb[k + 1] * sW1[(k + 1) * kH + c];
            a2 += rb[k + 2] * sW1[(k + 2) * kH + c];
            a3 += rb[k + 3] * sW1[(k + 3) * kH + c];
        }
        sh[half * kH + c] = silu(a0 + a1 + a2 + a3 + bb1);
        __syncthreads();
        float o0 = 0, o1 = 0, o2 = 0, o3 = 0;
        const float* hh = sh + half * kH;
#pragma unroll
        for (int j = 0; j < kH; j += 4) {
            o0 += hh[j + 0] * sW2[(j + 0) * kH + c];
            o1 += hh[j + 1] * sW2[(j + 1) * kH + c];
            o2 += hh[j + 2] * sW2[(j + 2) * kH + c];
            o3 += hh[j + 3] * sW2[(j + 3) * kH + c];
        }
        g_tabh[(blk * kNGRID + g) * kH + c] = __float2half_rn(o0 + o1 + o2 + o3 + bb2);
        __syncthreads();
    }
}

// ---------------- MMA GEMM: hs = h @ lin_in[0], fp16 out (tensor-core pilot) ----------------
// 64-row tile, 256 thr (8 warps). W transposed to fp16 smem Wt[n][k], row stride 136.
// Split-A: D = Ah*W16 + Al*W16 (2x mma.m16n8k16) -> weight-quant-only error.
#define kRSW 136
__global__ void __launch_bounds__(256) gemm_h_kernel(const float* __restrict__ A,
                                                     const float* __restrict__ W,
                                                     __half* __restrict__ C) {
    extern __shared__ __half Wt[];   // [128][kRSW] fp16
    int tid = threadIdx.x;
    int m0  = blockIdx.x * 64;

    // stage W transposed: fp32 [k][n] -> fp16 Wt[n][k]
#pragma unroll
    for (int it = 0; it < 16; it++) {
        int i  = tid + it * 256;        // 4096 float4 loads
        int k  = i >> 5;                // 0..127
        int n4 = (i & 31) << 2;         // 0,4,...,124
        float4 w = ((const float4*)W)[i];
        Wt[(n4 + 0) * kRSW + k] = __float2half_rn(w.x);
        Wt[(n4 + 1) * kRSW + k] = __float2half_rn(w.y);
        Wt[(n4 + 2) * kRSW + k] = __float2half_rn(w.z);
        Wt[(n4 + 3) * kRSW + k] = __float2half_rn(w.w);
    }
    __syncthreads();

    int warp = tid >> 5, lane = tid & 31;
    int gr = lane >> 2, ct = lane & 3;
    int r0 = (warp & 3) * 16;           // row group of 16
    int n0 = (warp >> 2) * 64;          // col half

    float acc[8][4];
#pragma unroll
    for (int nt = 0; nt < 8; nt++)
#pragma unroll
        for (int j = 0; j < 4; j++) acc[nt][j] = 0.0f;

    const float* Ar0 = A + (m0 + r0 + gr) * kH;
    const float* Ar8 = Ar0 + 8 * kH;

#pragma unroll
    for (int kc = 0; kc < 8; kc++) {
        int k0 = kc * 16 + 2 * ct;
        float2 f0 = *(const float2*)(Ar0 + k0);
        float2 f1 = *(const float2*)(Ar8 + k0);
        float2 f2 = *(const float2*)(Ar0 + k0 + 8);
        float2 f3 = *(const float2*)(Ar8 + k0 + 8);
        unsigned ah[4], al[4];
        split2(f0, ah[0], al[0]);
        split2(f1, ah[1], al[1]);
        split2(f2, ah[2], al[2]);
        split2(f3, ah[3], al[3]);
#pragma unroll
        for (int nt = 0; nt < 8; nt++) {
            const __half* bp = Wt + (n0 + nt * 8 + gr) * kRSW + kc * 16 + 2 * ct;
            unsigned b0 = *(const unsigned*)bp;
            unsigned b1 = *(const unsigned*)(bp + 8);
            mma16816(acc[nt], ah, b0, b1);
            mma16816(acc[nt], al, b0, b1);
        }
    }

#pragma unroll
    for (int nt = 0; nt < 8; nt++) {
        int row = m0 + r0 + gr;
        int col = n0 + nt * 8 + 2 * ct;
        __half2 h01 = __floats2half2_rn(acc[nt][0], acc[nt][1]);
        __half2 h23 = __floats2half2_rn(acc[nt][2], acc[nt][3]);
        *(__half2*)(C + row * kH + col)       = h01;
        *(__half2*)(C + (row + 8) * kH + col) = h23;
    }
}

// ---------------- edge aggregation: warp/node, fp16 table + fp16 hs ----------------
__global__ void __launch_bounds__(128) agg_kernel(int blk) {
    int warp = threadIdx.x >> 5;
    int lane = threadIdx.x & 31;
    int n    = blockIdx.x * 4 + warp;
    const uint2* tab = (const uint2*)(g_tabh + blk * kNGRID * kH);
    const uint2* hs  = (const uint2*)g_hsh;
    int len  = g_deg[n];
    if (len > kCAP) len = kCAP;
    const SEdge* row = g_se + n * kCAP;
    float4 acc = make_float4(0.f, 0.f, 0.f, 0.f);
    for (int p = 0; p < len; p++) {
        SEdge e = row[p];
        float t = e.t;
        int   gdx = (int)t;
        if (gdx > kNGRID - 2) gdx = kNGRID - 2;
        float f = t - (float)gdx;
        uint2 u0 = tab[gdx * 32 + lane];
        uint2 u1 = tab[(gdx + 1) * 32 + lane];
        uint2 uh = hs[e.s * 32 + lane];
        float2 w0a = __half22float2(*reinterpret_cast<__half2*>(&u0.x));
        float2 w0b = __half22float2(*reinterpret_cast<__half2*>(&u0.y));
        float2 w1a = __half22float2(*reinterpret_cast<__half2*>(&u1.x));
        float2 w1b = __half22float2(*reinterpret_cast<__half2*>(&u1.y));
        float2 hva = __half22float2(*reinterpret_cast<__half2*>(&uh.x));
        float2 hvb = __half22float2(*reinterpret_cast<__half2*>(&uh.y));
        acc.x += (w0a.x + (w1a.x - w0a.x) * f) * hva.x;
        acc.y += (w0a.y + (w1a.y - w0a.y) * f) * hva.y;
        acc.z += (w0b.x + (w1b.x - w0b.x) * f) * hvb.x;
        acc.w += (w0b.y + (w1b.y - w0b.y) * f) * hvb.y;
    }
    ((float4*)g_agg)[n * 32 + lane] = acc;
}

// ---------------- fused node MLP + residual + LayerNorm + next lin_in ----------------
// stage1: t1 = silu(agg@W1+b1) (smem); stage2: h = LN(h + t1@W2+b2);
// stage3 (if !LAST): hs = h @ Wnext -> fp16          (R6-proven SIMT version)
template <int LAST>
__global__ void __launch_bounds__(256) node_fused_kernel(
        const float* __restrict__ W1, const float* __restrict__ b1,
        const float* __restrict__ W2, const float* __restrict__ b2,
        const float* __restrict__ lng, const float* __restrict__ lnb,
        const float* __restrict__ Wnext) {
    extern __shared__ float sm[];
    float*  As  = sm;                       // 64*128 fp32 (agg -> t1 -> h)
    __half* Bsh = (__half*)(sm + 64 * kH);  // 128*128 fp16 (W1 -> W2 -> Wnext)
    int tid = threadIdx.x;
    int m0  = blockIdx.x * 64;
    int ty  = tid >> 4;
    int tx  = tid & 15;

    const float4* A4  = (const float4*)(g_agg + m0 * kH);
    float4*       As4 = (float4*)As;
#pragma unroll
    for (int i = 0; i < 8; i++) As4[tid + i * 256] = A4[tid + i * 256];
    load_w_half(W1, Bsh, tid);
    __syncthreads();

    float acc[4][8];
#pragma unroll
    for (int i = 0; i < 4; i++)
#pragma unroll
        for (int j = 0; j < 8; j++) acc[i][j] = 0.0f;
#pragma unroll 8
    for (int k = 0; k < kH; k++) {
        float av[4];
#pragma unroll
        for (int i = 0; i < 4; i++) av[i] = As[(ty * 4 + i) * kH + k];
        float bv[8];
        read_w8(Bsh, k, tx, bv);
#pragma unroll
        for (int i = 0; i < 4; i++)
#pragma unroll
            for (int j = 0; j < 8; j++) acc[i][j] += av[i] * bv[j];
    }
    __syncthreads();

    // t1 = silu(acc + b1) -> As ; W2 -> Bsh
    {
        float4 bb0 = *(const float4*)&b1[tx * 8];
        float4 bb1 = *(const float4*)&b1[tx * 8 + 4];
        float bb[8] = {bb0.x, bb0.y, bb0.z, bb0.w, bb1.x, bb1.y, bb1.z, bb1.w};
#pragma unroll
        for (int i = 0; i < 4; i++) {
            int r = ty * 4 + i;
#pragma unroll
            for (int j = 0; j < 8; j++)
                As[r * kH + tx * 8 + j] = silu(acc[i][j] + bb[j]);
        }
        load_w_half(W2, Bsh, tid);
    }
    __syncthreads();

#pragma unroll
    for (int i = 0; i < 4; i++)
#pragma unroll
        for (int j = 0; j < 8; j++) acc[i][j] = 0.0f;
#pragma unroll 8
    for (int k = 0; k < kH; k++) {
        float av[4];
#pragma unroll
        for (int i = 0; i < 4; i++) av[i] = As[(ty * 4 + i) * kH + k];
        float bv[8];
        read_w8(Bsh, k, tx, bv);
#pragma unroll
        for (int i = 0; i < 4; i++)
#pragma unroll
            for (int j = 0; j < 8; j++) acc[i][j] += av[i] * bv[j];
    }
    __syncthreads();   // stage-2 reads of As/Bsh done; safe to overwrite

    // epilogue: + b2 + residual, LayerNorm across 16 tx-threads per row
    float4 bb0 = *(const float4*)&b2[tx * 8];
    float4 bb1 = *(const float4*)&b2[tx * 8 + 4];
    float bb[8] = {bb0.x, bb0.y, bb0.z, bb0.w, bb1.x, bb1.y, bb1.z, bb1.w};
    float4 gg0 = *(const float4*)&lng[tx * 8];
    float4 gg1 = *(const float4*)&lng[tx * 8 + 4];
    float gg[8] = {gg0.x, gg0.y, gg0.z, gg0.w, gg1.x, gg1.y, gg1.z, gg1.w};
    float4 lb0 = *(const float4*)&lnb[tx * 8];
    float4 lb1 = *(const float4*)&lnb[tx * 8 + 4];
    float lb[8] = {lb0.x, lb0.y, lb0.z, lb0.w, lb1.x, lb1.y, lb1.z, lb1.w};

#pragma unroll
    for (int i = 0; i < 4; i++) {
        int r = m0 + ty * 4 + i;
        float4 h0 = *(const float4*)&g_h[r * kH + tx * 8];
        float4 h1 = *(const float4*)&g_h[r * kH + tx * 8 + 4];
        float hv[8] = {h0.x, h0.y, h0.z, h0.w, h1.x, h1.y, h1.z, h1.w};
        float v[8];
        float s = 0.0f;
#pragma unroll
        for (int j = 0; j < 8; j++) { v[j] = acc[i][j] + bb[j] + hv[j]; s += v[j]; }
#pragma unroll
        for (int o = 1; o < 16; o <<= 1) s += __shfl_xor_sync(0xffffffffu, s, o);
        float mu = s * (1.0f / 128.0f);
        float q = 0.0f;
        float d[8];
#pragma unroll
        for (int j = 0; j < 8; j++) { d[j] = v[j] - mu; q += d[j] * d[j]; }
#pragma unroll
        for (int o = 1; o < 16; o <<= 1) q += __shfl_xor_sync(0xffffffffu, q, o);
        float rstd = rsqrtf(q * (1.0f / 128.0f) + 1e-5f);
        float w[8];
#pragma unroll
        for (int j = 0; j < 8; j++) w[j] = d[j] * rstd * gg[j] + lb[j];
        *(float4*)&g_h[r * kH + tx * 8]     = make_float4(w[0], w[1], w[2], w[3]);
        *(float4*)&g_h[r * kH + tx * 8 + 4] = make_float4(w[4], w[5], w[6], w[7]);
        if (!LAST) {
            int rl = ty * 4 + i;
#pragma unroll
            for (int j = 0; j < 8; j++) As[rl * kH + tx * 8 + j] = w[j];
        }
    }

    if (!LAST) {
        load_w_half(Wnext, Bsh, tid);
        __syncthreads();

#pragma unroll
        for (int i = 0; i < 4; i++)
#pragma unroll
            for (int j = 0; j < 8; j++) acc[i][j] = 0.0f;
#pragma unroll 8
        for (int k = 0; k < kH; k++) {
            float av[4];
#pragma unroll
            for (int i = 0; i < 4; i++) av[i] = As[(ty * 4 + i) * kH + k];
            float bv[8];
            read_w8(Bsh, k, tx, bv);
#pragma unroll
            for (int i = 0; i < 4; i++)
#pragma unroll
                for (int j = 0; j < 8; j++) acc[i][j] += av[i] * bv[j];
        }
#pragma unroll
        for (int i = 0; i < 4; i++) {
            int r = m0 + ty * 4 + i;
            __half2 p0 = __floats2half2_rn(acc[i][0], acc[i][1]);
            __half2 p1 = __floats2half2_rn(acc[i][2], acc[i][3]);
            __half2 p2 = __floats2half2_rn(acc[i][4], acc[i][5]);
            __half2 p3 = __floats2half2_rn(acc[i][6], acc[i][7]);
            uint4 u;
            u.x = *reinterpret_cast<unsigned*>(&p0);
            u.y = *reinterpret_cast<unsigned*>(&p1);
            u.z = *reinterpret_cast<unsigned*>(&p2);
            u.w = *reinterpret_cast<unsigned*>(&p3);
            *reinterpret_cast<uint4*>(&g_hsh[r * kH + tx * 8]) = u;
        }
    }
}

// ---------------- readout ----------------
__global__ void readout_kernel(float* __restrict__ out,
                               const float* __restrict__ w1, const float* __restrict__ b1,
                               const float* __restrict__ w2, const float* __restrict__ b2) {
    __shared__ float s[kH];
    __shared__ float red[2];
    int n   = blockIdx.x;
    int tid = threadIdx.x;
    s[tid] = silu(g_h[n * kH + tid]);
    __syncthreads();
    float e = 0.0f;
    if (tid < 64) {
        float x = b1[tid];
#pragma unroll 8
        for (int k = 0; k < kH; k++) x += s[k] * w1[k * 64 + tid];
        e = silu(x) * w2[tid];
    }
#pragma unroll
    for (int off = 16; off; off >>= 1) e += __shfl_down_sync(0xffffffffu, e, off);
    if (tid == 0)  red[0] = e;
    if (tid == 32) red[1] = e;
    __syncthreads();
    if (tid == 0) atomicAdd(&out[n >> 7], red[0] + red[1] + b2[0]);
}

// ---------------- launcher ----------------
extern "C" void kernel_launch(void* const* d_in, const int* in_sizes, int n_in,
                              void* d_out, int out_size) {
    (void)in_sizes; (void)n_in; (void)out_size;
    const int*   Z        = (const int*)  d_in[0];
    const float* pos      = (const float*)d_in[1];
    const int*   ei       = (const int*)  d_in[2];
    const float* embed_w  = (const float*)d_in[3];
    const float* edge_w1  = (const float*)d_in[4];
    const float* edge_b1  = (const float*)d_in[5];
    const float* edge_w2  = (const float*)d_in[6];
    const float* edge_b2  = (const float*)d_in[7];
    const float* lin_in_w = (const float*)d_in[8];
    const float* node_w1  = (const float*)d_in[9];
    const float* node_b1  = (const float*)d_in[10];
    const float* node_w2  = (const float*)d_in[11];
    const float* node_b2  = (const float*)d_in[12];
    const float* ln_g     = (const float*)d_in[13];
    const float* ln_b     = (const float*)d_in[14];
    const float* ro_w1    = (const float*)d_in[15];
    const float* ro_b1    = (const float*)d_in[16];
    const float* ro_w2    = (const float*)d_in[17];
    const float* ro_b2    = (const float*)d_in[18];
    float* out = (float*)d_out;

    float *ph;
    __half *phs;
    cudaGetSymbolAddress((void**)&ph,  g_h);
    cudaGetSymbolAddress((void**)&phs, g_hsh);

    const int NODE_SMEM = 64 * kH * (int)sizeof(float) + kH * kH * (int)sizeof(__half); // 64 KB
    const int MMA_SMEM  = kH * kRSW * (int)sizeof(__half);                              // ~34 KB
    const int TAB_SMEM  = (kNRBF * kH + kH * kH + 2 * kH + 2 * kNRBF) * (int)sizeof(float);
    cudaFuncSetAttribute(gemm_h_kernel,        cudaFuncAttributeMaxDynamicSharedMemorySize, MMA_SMEM);
    cudaFuncSetAttribute(node_fused_kernel<0>, cudaFuncAttributeMaxDynamicSharedMemorySize, NODE_SMEM);
    cudaFuncSetAttribute(node_fused_kernel<1>, cudaFuncAttributeMaxDynamicSharedMemorySize, NODE_SMEM);
    cudaFuncSetAttribute(table_kernel,         cudaFuncAttributeMaxDynamicSharedMemorySize, TAB_SMEM);

    // ---- prep: embedding (+deg zero), bucket scatter, filter tables ----
    embed_kernel<<<kBN, kH>>>(Z, embed_w);
    scatter_kernel<<<kE / 512, 256>>>(ei, pos);
    table_kernel<<<dim3(kNGRID / 32, kNBLK), 256, TAB_SMEM>>>(edge_w1, edge_b1, edge_w2, edge_b2);
    gemm_h_kernel<<<kBN / 64, 256, MMA_SMEM>>>(ph, lin_in_w, phs);   // hs for block 0 (mma pilot)

    // ---- 4 interaction blocks ----
    for (int b = 0; b < kNBLK; b++) {
        agg_kernel<<<kBN / 4, 128>>>(b);
        if (b < kNBLK - 1) {
            node_fused_kernel<0><<<kBN / 64, 256, NODE_SMEM>>>(
                node_w1 + b * kH * kH, node_b1 + b * kH,
                node_w2 + b * kH * kH, node_b2 + b * kH,
                ln_g + b * kH, ln_b + b * kH,
                lin_in_w + (b + 1) * kH * kH);
        } else {
            node_fused_kernel<1><<<kBN / 64, 256, NODE_SMEM>>>(
                node_w1 + b * kH * kH, node_b1 + b * kH,
                node_w2 + b * kH * kH, node_b2 + b * kH,
                ln_g + b * kH, ln_b + b * kH, nullptr);
        }
    }

    // ---- readout ----
    zero_out_kernel<<<1, 64>>>(out);
    readout_kernel<<<kBN, kH>>>(out, ro_w1, ro_b1, ro_w2, ro_b2);
}